// round 15
// baseline (speedup 1.0000x reference)
#include <cuda_runtime.h>
#include <cuda_bf16.h>
#include <cuda_fp16.h>
#include <math.h>
#include <stdint.h>

#define B_   16
#define C_   512
#define N_   4096
#define NH_  8
#define HD_  64
#define NG_  8
#define CPG_ 64
#define EPS_ 1e-5f
#define NCH_ 8
#define NCW_ (N_ / NCH_)
#define NTK_ 8                                     // k-tiles of 64

#define BS_S 136                                   // Bs word stride: 8 mod 32 -> conflict-free
#define GEMM_SM ((3 * 4096 + 3 * 32 * BS_S) * 4)   // 101376 B

// Scratch (allocation-free: static device globals)
__device__ uint32_t g_qk2[(size_t)B_ * 2 * C_ * (N_/2)];  // q,k fp16x2 n-pairs
__device__ uint32_t g_v2 [(size_t)B_ * (C_/2) * N_];      // v fp16x2 e-pairs
__device__ uint32_t g_hv2[(size_t)B_ * (C_/2) * N_];      // hv fp16x2 c-pairs
__device__ uint32_t g_x2 [(size_t)B_ * (C_/2) * N_];      // (sc*x) fp16x2 c-pairs
__device__ float    g_sc[B_ * C_], g_sf[B_ * C_];
__device__ uint32_t g_wqh[3 * C_ * C_ / 2];               // w_qkv fp16 frag-packed
__device__ float    g_bqb[B_ * 3 * C_];
__device__ uint32_t g_wo2[C_ * C_ / 2];                   // w_out fp16 frag-packed
__device__ float    g_Sp[(size_t)B_ * NH_ * NCH_ * 64 * 64];
__device__ uint32_t g_P2[(size_t)B_ * NH_ * 64 * 32];     // P fp16x2 e-pairs

// ---------------- helpers ----------------
__device__ __forceinline__ void mma16h(float c[4], uint32_t a0, uint32_t a1,
                                       uint32_t a2, uint32_t a3,
                                       uint32_t b0, uint32_t b1) {
    asm volatile(
        "mma.sync.aligned.m16n8k16.row.col.f32.f16.f16.f32 "
        "{%0,%1,%2,%3}, {%4,%5,%6,%7}, {%8,%9}, {%0,%1,%2,%3};\n"
        : "+f"(c[0]), "+f"(c[1]), "+f"(c[2]), "+f"(c[3])
        : "r"(a0), "r"(a1), "r"(a2), "r"(a3), "r"(b0), "r"(b1));
}
__device__ __forceinline__ void cp16(uint32_t dst, const void* src) {
    asm volatile("cp.async.cg.shared.global [%0], [%1], 16;\n" :: "r"(dst), "l"(src));
}
__device__ __forceinline__ void cp_commit() {
    asm volatile("cp.async.commit_group;\n" ::: "memory");
}
__device__ __forceinline__ void cp_wait0() {
    asm volatile("cp.async.wait_group 0;\n" ::: "memory");
}
__device__ __forceinline__ void cp_wait1() {
    asm volatile("cp.async.wait_group 1;\n" ::: "memory");
}
__device__ __forceinline__ uint32_t packh2(float lo, float hi) {
    __half2 v = __floats2half2_rn(lo, hi);
    return *(uint32_t*)&v;
}

// ---------------- kernel 1: groupnorm stats + fused (sc*x) fp16 pack ----------------
__global__ __launch_bounds__(256) void gn_stats_kernel(
    const float* __restrict__ x, const float* __restrict__ gamma,
    const float* __restrict__ beta)
{
    int bg = blockIdx.x, b = bg / NG_, g = bg % NG_;
    int tid = threadIdx.x;
    const float* xg = x + ((size_t)b * C_ + (size_t)g * CPG_) * N_;
    const float4* xp = (const float4*)xg;
    const int total4 = CPG_ * N_ / 4;

    float s = 0.f, ss = 0.f;
    for (int i = tid; i < total4; i += 256) {
        float4 v = xp[i];
        s += v.x + v.y + v.z + v.w;
        ss += v.x*v.x + v.y*v.y + v.z*v.z + v.w*v.w;
    }
    __shared__ float sh_s[256], sh_q[256], sh_sc[CPG_];
    sh_s[tid] = s; sh_q[tid] = ss;
    __syncthreads();
    for (int off = 128; off > 0; off >>= 1) {
        if (tid < off) { sh_s[tid] += sh_s[tid+off]; sh_q[tid] += sh_q[tid+off]; }
        __syncthreads();
    }
    float inv_n = 1.f / (float)(CPG_ * N_);
    float mean = sh_s[0] * inv_n;
    float rstd = rsqrtf(sh_q[0] * inv_n - mean * mean + EPS_);
    if (tid < CPG_) {
        int c = g * CPG_ + tid;
        float ga = gamma[c];
        float sc = rstd * ga;
        g_sc[b * C_ + c] = sc;
        g_sf[b * C_ + c] = beta[c] - mean * rstd * ga;
        sh_sc[tid] = sc;
    }
    __syncthreads();

    // fused pack: (sc*x) -> fp16x2 c-pairs (re-read hits L2)
    uint32_t* xo = g_x2 + ((size_t)b * 256 + g * 32) * N_;
    for (int i = tid; i < 32 * (N_ / 4); i += 256) {
        int c2l = i >> 10, n4 = i & 1023;
        float s0 = sh_sc[2 * c2l], s1 = sh_sc[2 * c2l + 1];
        const float* r0 = xg + (size_t)(2 * c2l) * N_ + n4 * 4;
        float4 v0 = *(const float4*)r0;
        float4 v1 = *(const float4*)(r0 + N_);
        uint4 o;
        o.x = packh2(v0.x * s0, v1.x * s1); o.y = packh2(v0.y * s0, v1.y * s1);
        o.z = packh2(v0.z * s0, v1.z * s1); o.w = packh2(v0.w * s0, v1.w * s1);
        *(uint4*)(xo + (size_t)c2l * N_ + n4 * 4) = o;
    }
}

// ---------------- kernel 2a: W (qkv) -> fp16 frag-packed ----------------
__global__ __launch_bounds__(256) void wpack_h_kernel(const float* __restrict__ W)
{
    int w = blockIdx.x * 256 + threadIdx.x;
    if (w >= 3 * C_ * C_ / 2) return;
    int sel = w & 3, lane_p = (w >> 2) & 31, kt_g = (w >> 7) & 31, mt_g = w >> 12;
    int gid = lane_p >> 2, tig = lane_p & 3;
    int row = mt_g * 16 + gid + ((sel & 1) << 3);
    int k = kt_g * 16 + tig * 2 + ((sel >> 1) << 3);
    g_wqh[w] = packh2(W[(size_t)row * C_ + k], W[(size_t)row * C_ + k + 1]);
}

// ---------------- kernel 2b: bias fold  b' = bq + W @ sf ----------------
__global__ __launch_bounds__(256) void bias_fold_kernel(
    const float* __restrict__ W, const float* __restrict__ bq)
{
    int b = blockIdx.y;
    int wid = threadIdx.x >> 5, lane = threadIdx.x & 31;
    int o = blockIdx.x * 8 + wid;
    const float* sfl = g_sf + b * C_;
    float acc = 0.f;
    for (int j = 0; j < 16; j++) {
        int c = j * 32 + lane;
        acc += W[(size_t)o * C_ + c] * sfl[c];
    }
    #pragma unroll
    for (int off = 16; off > 0; off >>= 1)
        acc += __shfl_xor_sync(0xFFFFFFFF, acc, off);
    if (lane == 0) g_bqb[b * 3 * C_ + o] = bq[o] + acc;
}

// ---------------- kernel 3: w_out -> fp16 frag-packed ----------------
__global__ __launch_bounds__(256) void cvt_wo_kernel(const float* __restrict__ wo)
{
    int w = blockIdx.x * 256 + threadIdx.x;
    if (w >= C_ * C_ / 2) return;
    int sel = w & 3, lane_p = (w >> 2) & 31, kt_g = (w >> 7) & 31, mt_g = w >> 12;
    int gid = lane_p >> 2, tig = lane_p & 3;
    int row = mt_g * 16 + gid + ((sel & 1) << 3);
    int k = kt_g * 16 + tig * 2 + ((sel >> 1) << 3);
    g_wo2[w] = packh2(wo[(size_t)row * C_ + k], wo[(size_t)row * C_ + k + 1]);
}

// ---------------- fp16 GEMM (qkv): 128x128, BK=64, 3-stage, 2 CTA/SM ----------------
__global__ __launch_bounds__(256, 2) void gemm_qkv(void)
{
    extern __shared__ __align__(16) uint32_t smq[];
    uint32_t* As2 = smq;                    // 3*4096 words
    uint32_t* Bs2 = smq + 3 * 4096;         // 3*32*BS_S words

    int b = blockIdx.z, bm = blockIdx.y, bn = blockIdx.x;
    const float* bias = g_bqb + b * 3 * C_;

    int tid = threadIdx.x, lane = tid & 31, wid = tid >> 5;
    int gid = lane >> 2, tig = lane & 3;
    int m_warp = (wid >> 2) * 64, n_warp = (wid & 3) * 32;
    int mt_base = (wid >> 2) * 4;

    uint32_t As_base = (uint32_t)__cvta_generic_to_shared(As2);
    uint32_t Bs_base = (uint32_t)__cvta_generic_to_shared(Bs2);

    float acc[4][4][4];
    #pragma unroll
    for (int mt = 0; mt < 4; mt++)
        #pragma unroll
        for (int nt = 0; nt < 4; nt++)
            #pragma unroll
            for (int r = 0; r < 4; r++) acc[mt][nt][r] = 0.f;

    auto issue = [&](int kt, int s) {
        #pragma unroll
        for (int l = 0; l < 4; l++) {
            int c = tid + l * 256;             // 0..1023
            int mt = c >> 7, w4 = c & 127;
            cp16(As_base + ((s * 4096) + mt * 512 + w4 * 4) * 4,
                 g_wqh + ((size_t)(bm * 8 + mt) * 32 + kt * 4) * 128 + w4 * 4);
        }
        #pragma unroll
        for (int l = 0; l < 4; l++) {
            int c = tid + l * 256;
            int r = c >> 5, n4 = c & 31;       // r 0..31
            cp16(Bs_base + ((s * 32 + r) * BS_S + n4 * 4) * 4,
                 g_x2 + ((size_t)b * 256 + kt * 32 + r) * N_ + bn * 128 + n4 * 4);
        }
        cp_commit();
    };

    issue(0, 0);
    issue(1, 1);
    for (int kt = 0; kt < NTK_; kt++) {
        if (kt == NTK_ - 1) cp_wait0(); else cp_wait1();
        __syncthreads();
        if (kt + 2 < NTK_) issue(kt + 2, (kt + 2) % 3);
        int buf = kt % 3;

        #pragma unroll
        for (int ks = 0; ks < 4; ks++) {
            int kb2 = ks * 8;
            uint4 af[4];
            uint32_t bf[4][2];
            #pragma unroll
            for (int mt = 0; mt < 4; mt++)
                af[mt] = *(const uint4*)(As2 + buf * 4096 +
                                         (mt_base + mt) * 512 + ks * 128 + lane * 4);
            #pragma unroll
            for (int nt = 0; nt < 4; nt++) {
                int n0 = n_warp + nt * 8 + gid;
                bf[nt][0] = Bs2[(buf * 32 + kb2 + tig) * BS_S + n0];
                bf[nt][1] = Bs2[(buf * 32 + kb2 + tig + 4) * BS_S + n0];
            }
            #pragma unroll
            for (int mt = 0; mt < 4; mt++)
                #pragma unroll
                for (int nt = 0; nt < 4; nt++)
                    mma16h(acc[mt][nt], af[mt].x, af[mt].y, af[mt].z, af[mt].w,
                           bf[nt][0], bf[nt][1]);
        }
    }

    if (bm < 8) {
        #pragma unroll
        for (int mt = 0; mt < 4; mt++) {
            int r0 = m_warp + mt * 16 + gid;
            int gr0 = bm * 128 + r0;
            float bi0 = bias[gr0], bi1 = bias[gr0 + 8];
            #pragma unroll
            for (int nt = 0; nt < 4; nt++) {
                int col = n_warp + nt * 8 + tig * 2;
                uint32_t* o = g_qk2 + ((size_t)b * 2 * C_ + gr0) * (N_ / 2)
                              + bn * 64 + (col >> 1);
                o[0] = packh2(acc[mt][nt][0] + bi0, acc[mt][nt][1] + bi0);
                o[8 * (N_ / 2)] = packh2(acc[mt][nt][2] + bi1, acc[mt][nt][3] + bi1);
            }
        }
    } else {
        #pragma unroll
        for (int mt = 0; mt < 4; mt++) {
            int r0 = m_warp + mt * 16 + gid;
            int o_glob = bm * 128 + r0;
            float bi0 = bias[o_glob], bi1 = bias[o_glob + 8];
            int ch = (bm - 8) * 128 + m_warp + mt * 16 + gid;
            #pragma unroll
            for (int nt = 0; nt < 4; nt++) {
                int col = n_warp + nt * 8 + tig * 2;
                float v00 = acc[mt][nt][0] + bi0;
                float v01 = acc[mt][nt][1] + bi0;
                float v10 = acc[mt][nt][2] + bi1;
                float v11 = acc[mt][nt][3] + bi1;
                float n00 = __shfl_down_sync(0xFFFFFFFF, v00, 4);
                float n01 = __shfl_down_sync(0xFFFFFFFF, v01, 4);
                float n10 = __shfl_down_sync(0xFFFFFFFF, v10, 4);
                float n11 = __shfl_down_sync(0xFFFFFFFF, v11, 4);
                if (!(gid & 1)) {
                    uint32_t* o0 = g_v2 + ((size_t)b * 256 + (ch >> 1)) * N_
                                   + bn * 128 + col;
                    *(uint2*)o0 = make_uint2(packh2(v00, n00), packh2(v01, n01));
                    uint32_t* o1 = g_v2 + ((size_t)b * 256 + ((ch + 8) >> 1)) * N_
                                   + bn * 128 + col;
                    *(uint2*)o1 = make_uint2(packh2(v10, n10), packh2(v11, n11));
                }
            }
        }
    }
}

// ---------------- fp16 GEMM (out proj): 128x128, BK=64, 3-stage, 2 CTA/SM ----------------
__global__ __launch_bounds__(256, 2) void gemm_out(
    const float* __restrict__ bias, const float* __restrict__ resid,
    float* __restrict__ Out)
{
    extern __shared__ __align__(16) uint32_t smo[];
    uint32_t* As2 = smo;
    uint32_t* Bs2 = smo + 3 * 4096;

    int b = blockIdx.z, bm = blockIdx.y, bn = blockIdx.x;
    int tid = threadIdx.x, lane = tid & 31, wid = tid >> 5;
    int gid = lane >> 2, tig = lane & 3;
    int m_warp = (wid >> 2) * 64, n_warp = (wid & 3) * 32;
    int mt_base = (wid >> 2) * 4;

    uint32_t As_base = (uint32_t)__cvta_generic_to_shared(As2);
    uint32_t Bs_base = (uint32_t)__cvta_generic_to_shared(Bs2);

    float acc[4][4][4];
    #pragma unroll
    for (int mt = 0; mt < 4; mt++)
        #pragma unroll
        for (int nt = 0; nt < 4; nt++)
            #pragma unroll
            for (int r = 0; r < 4; r++) acc[mt][nt][r] = 0.f;

    auto issue = [&](int kt, int s) {
        #pragma unroll
        for (int l = 0; l < 4; l++) {
            int c = tid + l * 256;
            int mt = c >> 7, w4 = c & 127;
            cp16(As_base + ((s * 4096) + mt * 512 + w4 * 4) * 4,
                 g_wo2 + ((size_t)(bm * 8 + mt) * 32 + kt * 4) * 128 + w4 * 4);
        }
        #pragma unroll
        for (int l = 0; l < 4; l++) {
            int c = tid + l * 256;
            int r = c >> 5, n4 = c & 31;
            cp16(Bs_base + ((s * 32 + r) * BS_S + n4 * 4) * 4,
                 g_hv2 + ((size_t)b * 256 + kt * 32 + r) * N_ + bn * 128 + n4 * 4);
        }
        cp_commit();
    };

    issue(0, 0);
    issue(1, 1);
    for (int kt = 0; kt < NTK_; kt++) {
        if (kt == NTK_ - 1) cp_wait0(); else cp_wait1();
        __syncthreads();
        if (kt + 2 < NTK_) issue(kt + 2, (kt + 2) % 3);
        int buf = kt % 3;

        #pragma unroll
        for (int ks = 0; ks < 4; ks++) {
            int kb2 = ks * 8;
            uint4 af[4];
            uint32_t bf[4][2];
            #pragma unroll
            for (int mt = 0; mt < 4; mt++)
                af[mt] = *(const uint4*)(As2 + buf * 4096 +
                                         (mt_base + mt) * 512 + ks * 128 + lane * 4);
            #pragma unroll
            for (int nt = 0; nt < 4; nt++) {
                int n0 = n_warp + nt * 8 + gid;
                bf[nt][0] = Bs2[(buf * 32 + kb2 + tig) * BS_S + n0];
                bf[nt][1] = Bs2[(buf * 32 + kb2 + tig + 4) * BS_S + n0];
            }
            #pragma unroll
            for (int mt = 0; mt < 4; mt++)
                #pragma unroll
                for (int nt = 0; nt < 4; nt++)
                    mma16h(acc[mt][nt], af[mt].x, af[mt].y, af[mt].z, af[mt].w,
                           bf[nt][0], bf[nt][1]);
        }
    }

    #pragma unroll
    for (int mt = 0; mt < 4; mt++) {
        int r0 = m_warp + mt * 16 + gid;
        int gr0 = bm * 128 + r0;
        float bi0 = bias[gr0], bi1 = bias[gr0 + 8];
        #pragma unroll
        for (int nt = 0; nt < 4; nt++) {
            int col = n_warp + nt * 8 + tig * 2;
            size_t base = ((size_t)b * C_ + gr0) * N_ + bn * 128 + col;
            float2 x0 = *(const float2*)(resid + base);
            float2 x1 = *(const float2*)(resid + base + 8 * N_);
            *(float2*)(Out + base) =
                make_float2(acc[mt][nt][0] + bi0 + x0.x, acc[mt][nt][1] + bi0 + x0.y);
            *(float2*)(Out + base + 8 * N_) =
                make_float2(acc[mt][nt][2] + bi1 + x1.x, acc[mt][nt][3] + bi1 + x1.y);
        }
    }
}

// ---------------- attention ----------------
#define SQ_S 68
#define QK_S 36

__global__ __launch_bounds__(256) void attn_qk_kernel()
{
    __shared__ uint32_t q2s[64 * QK_S], k2s[64 * QK_S];
    int chunk = blockIdx.x, bh = blockIdx.y;
    int b = bh / NH_, h = bh % NH_;
    const uint32_t* q2 = g_qk2 + ((size_t)b * 2 * C_ + h * HD_) * (N_ / 2) + chunk * (NCW_ / 2);
    const uint32_t* k2 = g_qk2 + ((size_t)b * 2 * C_ + C_ + h * HD_) * (N_ / 2) + chunk * (NCW_ / 2);

    int tid = threadIdx.x, lane = tid & 31, wid = tid >> 5;
    int gid = lane >> 2, tig = lane & 3;
    int m_warp = (wid & 3) * 16, n_warp = (wid >> 2) * 32;

    float acc[4][4];
    #pragma unroll
    for (int nt = 0; nt < 4; nt++)
        #pragma unroll
        for (int r = 0; r < 4; r++) acc[nt][r] = 0.f;

    uint4 rq[2], rk[2];
    #pragma unroll
    for (int l = 0; l < 2; l++) {
        int idx = tid + l * 256, row = idx >> 3, w4 = idx & 7;
        rq[l] = *(const uint4*)(q2 + (size_t)row * (N_ / 2) + w4 * 4);
        rk[l] = *(const uint4*)(k2 + (size_t)row * (N_ / 2) + w4 * 4);
    }

    for (int n0w = 0; n0w < NCW_ / 2; n0w += 32) {
        #pragma unroll
        for (int l = 0; l < 2; l++) {
            int idx = tid + l * 256, row = idx >> 3, w4 = idx & 7;
            *(uint4*)(q2s + row * QK_S + w4 * 4) = rq[l];
            *(uint4*)(k2s + row * QK_S + w4 * 4) = rk[l];
        }
        __syncthreads();
        if (n0w + 32 < NCW_ / 2) {
            #pragma unroll
            for (int l = 0; l < 2; l++) {
                int idx = tid + l * 256, row = idx >> 3, w4 = idx & 7;
                rq[l] = *(const uint4*)(q2 + (size_t)row * (N_ / 2) + n0w + 32 + w4 * 4);
                rk[l] = *(const uint4*)(k2 + (size_t)row * (N_ / 2) + n0w + 32 + w4 * 4);
            }
        }
        #pragma unroll
        for (int ks = 0; ks < 4; ks++) {
            int kb = ks * 8;
            uint32_t a0 = q2s[(m_warp + gid) * QK_S + kb + tig];
            uint32_t a1 = q2s[(m_warp + gid + 8) * QK_S + kb + tig];
            uint32_t a2 = q2s[(m_warp + gid) * QK_S + kb + tig + 4];
            uint32_t a3 = q2s[(m_warp + gid + 8) * QK_S + kb + tig + 4];
            uint32_t bf[4][2];
            #pragma unroll
            for (int nt = 0; nt < 4; nt++) {
                int e0 = n_warp + nt * 8 + gid;
                bf[nt][0] = k2s[e0 * QK_S + kb + tig];
                bf[nt][1] = k2s[e0 * QK_S + kb + tig + 4];
            }
            #pragma unroll
            for (int nt = 0; nt < 4; nt++)
                mma16h(acc[nt], a0, a1, a2, a3, bf[nt][0], bf[nt][1]);
        }
        __syncthreads();
    }
    float* Sp = g_Sp + ((size_t)bh * NCH_ + chunk) * 4096;
    #pragma unroll
    for (int nt = 0; nt < 4; nt++) {
        int col = n_warp + nt * 8 + tig * 2, rA = m_warp + gid;
        *(float2*)(Sp + rA * 64 + col)       = make_float2(acc[nt][0], acc[nt][1]);
        *(float2*)(Sp + (rA + 8) * 64 + col) = make_float2(acc[nt][2], acc[nt][3]);
    }
}

__global__ __launch_bounds__(256) void attn_softmax_kernel()
{
    __shared__ float sS[64 * SQ_S];
    int bh = blockIdx.x, tid = threadIdx.x;
    const float* Sp = g_Sp + (size_t)bh * NCH_ * 4096;
    uint32_t* P2 = g_P2 + (size_t)bh * 2048;

    for (int i = tid * 4; i < 4096; i += 1024) {
        float4 s = *(const float4*)(Sp + i);
        #pragma unroll
        for (int c = 1; c < NCH_; c++) {
            float4 p = *(const float4*)(Sp + (size_t)c * 4096 + i);
            s.x += p.x; s.y += p.y; s.z += p.z; s.w += p.w;
        }
        int row = i >> 6, col = i & 63;
        s.x *= 0.125f; s.y *= 0.125f; s.z *= 0.125f; s.w *= 0.125f;
        *(float4*)(sS + row * SQ_S + col) = s;
    }
    __syncthreads();
    if (tid < 64) {
        int r = tid;
        float m = -1e30f;
        for (int c = 0; c < 64; c++) m = fmaxf(m, sS[r * SQ_S + c]);
        float s = 0.f, e[64];
        #pragma unroll 8
        for (int c = 0; c < 64; c++) { e[c] = __expf(sS[r * SQ_S + c] - m); s += e[c]; }
        float inv = 1.f / s;
        #pragma unroll 8
        for (int c2 = 0; c2 < 32; c2++)
            P2[r * 32 + c2] = packh2(e[2*c2] * inv, e[2*c2+1] * inv);
    }
}

__global__ __launch_bounds__(256) void attn_pv_kernel()
{
    __shared__ uint32_t p2s[64 * 36];
    __shared__ uint32_t v2s[32 * 72];
    __shared__ float    hs[64 * 66];

    int chunk = blockIdx.x, bh = blockIdx.y;
    int b = bh / NH_, h = bh % NH_;
    const uint32_t* v2 = g_v2 + ((size_t)b * 256 + h * 32) * N_ + chunk * NCW_;
    const uint32_t* P2 = g_P2 + (size_t)bh * 2048;
    uint32_t* hv2 = g_hv2 + ((size_t)b * 256 + h * 32) * N_ + chunk * NCW_;

    int tid = threadIdx.x, lane = tid & 31, wid = tid >> 5;
    int gid = lane >> 2, tig = lane & 3;
    int m_warp = (wid & 3) * 16, n_warp = (wid >> 2) * 32;

    for (int i = tid * 4; i < 2048; i += 1024) {
        int row = i >> 5, c2 = i & 31;
        *(uint4*)(p2s + row * 36 + c2) = *(const uint4*)(P2 + i);
    }
    uint4 rv[2];
    #pragma unroll
    for (int l = 0; l < 2; l++) {
        int idx = tid + l * 256, row = idx >> 4, w4 = idx & 15;
        rv[l] = *(const uint4*)(v2 + (size_t)row * N_ + w4 * 4);
    }
    __syncthreads();

    uint32_t pa[4][4];
    #pragma unroll
    for (int ks = 0; ks < 4; ks++) {
        int kc = ks * 8;
        pa[ks][0] = p2s[(m_warp + gid) * 36 + kc + tig];
        pa[ks][1] = p2s[(m_warp + gid + 8) * 36 + kc + tig];
        pa[ks][2] = p2s[(m_warp + gid) * 36 + kc + tig + 4];
        pa[ks][3] = p2s[(m_warp + gid + 8) * 36 + kc + tig + 4];
    }

    for (int n0 = 0; n0 < NCW_; n0 += 64) {
        #pragma unroll
        for (int l = 0; l < 2; l++) {
            int idx = tid + l * 256, row = idx >> 4, w4 = idx & 15;
            *(uint4*)(v2s + row * 72 + w4 * 4) = rv[l];
        }
        __syncthreads();
        if (n0 + 64 < NCW_) {
            #pragma unroll
            for (int l = 0; l < 2; l++) {
                int idx = tid + l * 256, row = idx >> 4, w4 = idx & 15;
                rv[l] = *(const uint4*)(v2 + (size_t)row * N_ + n0 + 64 + w4 * 4);
            }
        }
        float a2[4][4];
        #pragma unroll
        for (int nt = 0; nt < 4; nt++)
            #pragma unroll
            for (int r = 0; r < 4; r++) a2[nt][r] = 0.f;

        #pragma unroll
        for (int ks = 0; ks < 4; ks++) {
            int kc = ks * 8;
            uint32_t bf[4][2];
            #pragma unroll
            for (int nt = 0; nt < 4; nt++) {
                int nn = n_warp + nt * 8 + gid;
                bf[nt][0] = v2s[(kc + tig) * 72 + nn];
                bf[nt][1] = v2s[(kc + tig + 4) * 72 + nn];
            }
            #pragma unroll
            for (int nt = 0; nt < 4; nt++)
                mma16h(a2[nt], pa[ks][0], pa[ks][1], pa[ks][2], pa[ks][3],
                       bf[nt][0], bf[nt][1]);
        }
        #pragma unroll
        for (int nt = 0; nt < 4; nt++) {
            int col = n_warp + nt * 8 + tig * 2, rA = m_warp + gid;
            *(float2*)(hs + rA * 66 + col)       = make_float2(a2[nt][0], a2[nt][1]);
            *(float2*)(hs + (rA + 8) * 66 + col) = make_float2(a2[nt][2], a2[nt][3]);
        }
        __syncthreads();
        int n = tid & 63, c2b = tid >> 6;
        #pragma unroll
        for (int j = 0; j < 8; j++) {
            int c2 = c2b + j * 4;
            hv2[(size_t)c2 * N_ + n0 + n] =
                packh2(hs[(2*c2) * 66 + n], hs[(2*c2+1) * 66 + n]);
        }
        __syncthreads();
    }
}

// ---------------------------------------------------------------------------
extern "C" void kernel_launch(void* const* d_in, const int* in_sizes, int n_in,
                              void* d_out, int out_size)
{
    const float* x     = (const float*)d_in[0];
    const float* gamma = (const float*)d_in[1];
    const float* beta  = (const float*)d_in[2];
    const float* w_qkv = (const float*)d_in[3];
    const float* b_qkv = (const float*)d_in[4];
    const float* w_out = (const float*)d_in[5];
    const float* b_out = (const float*)d_in[6];
    float* out = (float*)d_out;

    static int configured = 0;
    if (!configured) {
        cudaFuncSetAttribute(gemm_qkv, cudaFuncAttributeMaxDynamicSharedMemorySize, GEMM_SM);
        cudaFuncSetAttribute(gemm_out, cudaFuncAttributeMaxDynamicSharedMemorySize, GEMM_SM);
        configured = 1;
    }

    cvt_wo_kernel<<<(C_ * C_ / 2 + 255) / 256, 256>>>(w_out);
    wpack_h_kernel<<<(3 * C_ * C_ / 2 + 255) / 256, 256>>>(w_qkv);
    gn_stats_kernel<<<B_ * NG_, 256>>>(x, gamma, beta);
    bias_fold_kernel<<<dim3(3 * C_ / 8, B_), 256>>>(w_qkv, b_qkv);
    gemm_qkv<<<dim3(N_ / 128, (3 * C_) / 128, B_), 256, GEMM_SM>>>();
    attn_qk_kernel<<<dim3(NCH_, B_ * NH_), 256>>>();
    attn_softmax_kernel<<<B_ * NH_, 256>>>();
    attn_pv_kernel<<<dim3(NCH_, B_ * NH_), 256>>>();
    gemm_out<<<dim3(N_ / 128, C_ / 128, B_), 256, GEMM_SM>>>(b_out, x, out);
}

// round 16
// speedup vs baseline: 1.1333x; 1.1333x over previous
#include <cuda_runtime.h>
#include <cuda_bf16.h>
#include <cuda_fp16.h>
#include <math.h>
#include <stdint.h>

#define B_   16
#define C_   512
#define N_   4096
#define NH_  8
#define HD_  64
#define NG_  8
#define CPG_ 64
#define EPS_ 1e-5f
#define NCH_ 8
#define NCW_ (N_ / NCH_)
#define NTK_ 16

#define BS_S 136                                   // Bs word stride: 8 mod 32 -> conflict-free
#define GEMM_SM ((3 * 2048 + 3 * 16 * BS_S) * 4)   // 50688 B

// Scratch (allocation-free: static device globals)
__device__ uint32_t g_qk2[(size_t)B_ * 2 * C_ * (N_/2)];  // q,k fp16x2 n-pairs
__device__ uint32_t g_v2 [(size_t)B_ * (C_/2) * N_];      // v fp16x2 e-pairs
__device__ uint32_t g_hv2[(size_t)B_ * (C_/2) * N_];      // hv fp16x2 c-pairs
__device__ uint32_t g_x2 [(size_t)B_ * (C_/2) * N_];      // (sc*x) fp16x2 c-pairs
__device__ float    g_sc[B_ * C_], g_sf[B_ * C_];
__device__ uint32_t g_wqh[3 * C_ * C_ / 2];               // w_qkv fp16 frag-packed
__device__ float    g_bqb[B_ * 3 * C_];
__device__ uint32_t g_wo2[C_ * C_ / 2];                   // w_out fp16 frag-packed
__device__ float    g_Sp[(size_t)B_ * NH_ * NCH_ * 64 * 64];
__device__ uint32_t g_P2[(size_t)B_ * NH_ * 64 * 32];     // P fp16x2 e-pairs

// ---------------- helpers ----------------
__device__ __forceinline__ void mma16h(float c[4], uint32_t a0, uint32_t a1,
                                       uint32_t a2, uint32_t a3,
                                       uint32_t b0, uint32_t b1) {
    asm volatile(
        "mma.sync.aligned.m16n8k16.row.col.f32.f16.f16.f32 "
        "{%0,%1,%2,%3}, {%4,%5,%6,%7}, {%8,%9}, {%0,%1,%2,%3};\n"
        : "+f"(c[0]), "+f"(c[1]), "+f"(c[2]), "+f"(c[3])
        : "r"(a0), "r"(a1), "r"(a2), "r"(a3), "r"(b0), "r"(b1));
}
__device__ __forceinline__ void cp16(uint32_t dst, const void* src) {
    asm volatile("cp.async.cg.shared.global [%0], [%1], 16;\n" :: "r"(dst), "l"(src));
}
__device__ __forceinline__ void cp_commit() {
    asm volatile("cp.async.commit_group;\n" ::: "memory");
}
__device__ __forceinline__ void cp_wait0() {
    asm volatile("cp.async.wait_group 0;\n" ::: "memory");
}
__device__ __forceinline__ void cp_wait1() {
    asm volatile("cp.async.wait_group 1;\n" ::: "memory");
}
__device__ __forceinline__ uint32_t packh2(float lo, float hi) {
    __half2 v = __floats2half2_rn(lo, hi);
    return *(uint32_t*)&v;
}

// ---------------- kernel 1: groupnorm stats -> sc/sf ----------------
__global__ __launch_bounds__(256) void gn_stats_kernel(
    const float* __restrict__ x, const float* __restrict__ gamma,
    const float* __restrict__ beta)
{
    int bg = blockIdx.x, b = bg / NG_, g = bg % NG_;
    int tid = threadIdx.x;
    const float4* xp = (const float4*)(x + ((size_t)b * C_ + (size_t)g * CPG_) * N_);
    const int total4 = CPG_ * N_ / 4;

    float s = 0.f, ss = 0.f;
    for (int i = tid; i < total4; i += 256) {
        float4 v = xp[i];
        s += v.x + v.y + v.z + v.w;
        ss += v.x*v.x + v.y*v.y + v.z*v.z + v.w*v.w;
    }
    __shared__ float sh_s[256], sh_q[256];
    sh_s[tid] = s; sh_q[tid] = ss;
    __syncthreads();
    for (int off = 128; off > 0; off >>= 1) {
        if (tid < off) { sh_s[tid] += sh_s[tid+off]; sh_q[tid] += sh_q[tid+off]; }
        __syncthreads();
    }
    float inv_n = 1.f / (float)(CPG_ * N_);
    float mean = sh_s[0] * inv_n;
    float rstd = rsqrtf(sh_q[0] * inv_n - mean * mean + EPS_);
    if (tid < CPG_) {
        int c = g * CPG_ + tid;
        float ga = gamma[c];
        g_sc[b * C_ + c] = rstd * ga;
        g_sf[b * C_ + c] = beta[c] - mean * rstd * ga;
    }
}

// ---------------- kernel 2a: pack w_qkv AND w_out -> fp16 frag layout ----------------
// 2 words per thread; grid covers (3*C*C/2 + C*C/2)/2 words.
__device__ __forceinline__ void pack_pair(uint32_t* dst, const float* W, int w) {
    int sel = w & 3, lane_p = (w >> 2) & 31, kt_g = (w >> 7) & 31, mt_g = w >> 12;
    int gid = lane_p >> 2, tig = lane_p & 3;
    int row = mt_g * 16 + gid + ((sel & 1) << 3);
    int k = kt_g * 16 + tig * 2 + ((sel >> 1) << 3);
    dst[w] = packh2(W[(size_t)row * C_ + k], W[(size_t)row * C_ + k + 1]);
}
__global__ __launch_bounds__(256) void wpack_all_kernel(
    const float* __restrict__ Wq, const float* __restrict__ Wo)
{
    const int NQ = 3 * C_ * C_ / 2;       // 393216
    const int NO = C_ * C_ / 2;           // 131072
    int t = blockIdx.x * 256 + threadIdx.x;
    int w0 = t * 2;
    if (w0 + 1 < NQ) {
        pack_pair(g_wqh, Wq, w0);
        pack_pair(g_wqh, Wq, w0 + 1);
    } else if (w0 >= NQ && w0 - NQ + 1 < NO) {
        pack_pair(g_wo2, Wo, w0 - NQ);
        pack_pair(g_wo2, Wo, w0 - NQ + 1);
    }
}

// ---------------- kernel 2b: bias fold  b' = bq + W @ sf ----------------
__global__ __launch_bounds__(256) void bias_fold_kernel(
    const float* __restrict__ W, const float* __restrict__ bq)
{
    int b = blockIdx.y;
    int wid = threadIdx.x >> 5, lane = threadIdx.x & 31;
    int o = blockIdx.x * 8 + wid;
    const float* sfl = g_sf + b * C_;
    float acc = 0.f;
    for (int j = 0; j < 16; j++) {
        int c = j * 32 + lane;
        acc += W[(size_t)o * C_ + c] * sfl[c];
    }
    #pragma unroll
    for (int off = 16; off > 0; off >>= 1)
        acc += __shfl_xor_sync(0xFFFFFFFF, acc, off);
    if (lane == 0) g_bqb[b * 3 * C_ + o] = bq[o] + acc;
}

// ---------------- kernel 2c: x -> (sc*x) fp16x2 c-pair packed ----------------
__global__ __launch_bounds__(256) void xpack_kernel(const float* __restrict__ x)
{
    int idx = blockIdx.x * 256 + threadIdx.x;
    int b = idx >> 18;
    int rem = idx & 0x3FFFF;
    int c2 = rem >> 10, n4 = rem & 1023;
    float s0 = g_sc[b * C_ + 2 * c2], s1 = g_sc[b * C_ + 2 * c2 + 1];
    const float* r0 = x + ((size_t)b * C_ + 2 * c2) * N_ + n4 * 4;
    float4 v0 = *(const float4*)r0;
    float4 v1 = *(const float4*)(r0 + N_);
    uint4 o;
    o.x = packh2(v0.x * s0, v1.x * s1); o.y = packh2(v0.y * s0, v1.y * s1);
    o.z = packh2(v0.z * s0, v1.z * s1); o.w = packh2(v0.w * s0, v1.w * s1);
    *(uint4*)(g_x2 + ((size_t)b * 256 + c2) * N_ + n4 * 4) = o;
}

// ---------------- fp16 GEMM (qkv): 128x128, BK=32, 3-stage, 2 CTA/SM ----------------
__global__ __launch_bounds__(256, 2) void gemm_qkv(void)
{
    extern __shared__ __align__(16) uint32_t smq[];
    uint32_t* As2 = smq;
    uint32_t* Bs2 = smq + 3 * 2048;

    int b = blockIdx.z, bm = blockIdx.y, bn = blockIdx.x;
    const float* bias = g_bqb + b * 3 * C_;

    int tid = threadIdx.x, lane = tid & 31, wid = tid >> 5;
    int gid = lane >> 2, tig = lane & 3;
    int m_warp = (wid >> 2) * 64, n_warp = (wid & 3) * 32;
    int mt_base = (wid >> 2) * 4;

    uint32_t As_base = (uint32_t)__cvta_generic_to_shared(As2);
    uint32_t Bs_base = (uint32_t)__cvta_generic_to_shared(Bs2);

    float acc[4][4][4];
    #pragma unroll
    for (int mt = 0; mt < 4; mt++)
        #pragma unroll
        for (int nt = 0; nt < 4; nt++)
            #pragma unroll
            for (int r = 0; r < 4; r++) acc[mt][nt][r] = 0.f;

    auto issue = [&](int kt, int s) {
        #pragma unroll
        for (int l = 0; l < 2; l++) {
            int c = tid + l * 256;
            int mt = c >> 6, w4 = c & 63;
            cp16(As_base + ((s * 2048) + mt * 256 + w4 * 4) * 4,
                 g_wqh + ((size_t)(bm * 8 + mt) * 32 + kt * 2) * 128 + w4 * 4);
        }
        #pragma unroll
        for (int l = 0; l < 2; l++) {
            int c = tid + l * 256;
            int r = c >> 5, n4 = c & 31;
            cp16(Bs_base + ((s * 16 + r) * BS_S + n4 * 4) * 4,
                 g_x2 + ((size_t)b * 256 + kt * 16 + r) * N_ + bn * 128 + n4 * 4);
        }
        cp_commit();
    };

    issue(0, 0);
    issue(1, 1);
    for (int kt = 0; kt < NTK_; kt++) {
        if (kt == NTK_ - 1) cp_wait0(); else cp_wait1();
        __syncthreads();
        if (kt + 2 < NTK_) issue(kt + 2, (kt + 2) % 3);
        int buf = kt % 3;

        #pragma unroll
        for (int ks = 0; ks < 2; ks++) {
            int kb2 = ks * 8;
            uint4 af[4];
            uint32_t bf[4][2];
            #pragma unroll
            for (int mt = 0; mt < 4; mt++)
                af[mt] = *(const uint4*)(As2 + buf * 2048 +
                                         (mt_base + mt) * 256 + ks * 128 + lane * 4);
            #pragma unroll
            for (int nt = 0; nt < 4; nt++) {
                int n0 = n_warp + nt * 8 + gid;
                bf[nt][0] = Bs2[(buf * 16 + kb2 + tig) * BS_S + n0];
                bf[nt][1] = Bs2[(buf * 16 + kb2 + tig + 4) * BS_S + n0];
            }
            #pragma unroll
            for (int mt = 0; mt < 4; mt++)
                #pragma unroll
                for (int nt = 0; nt < 4; nt++)
                    mma16h(acc[mt][nt], af[mt].x, af[mt].y, af[mt].z, af[mt].w,
                           bf[nt][0], bf[nt][1]);
        }
    }

    if (bm < 8) {
        #pragma unroll
        for (int mt = 0; mt < 4; mt++) {
            int r0 = m_warp + mt * 16 + gid;
            int gr0 = bm * 128 + r0;
            float bi0 = bias[gr0], bi1 = bias[gr0 + 8];
            #pragma unroll
            for (int nt = 0; nt < 4; nt++) {
                int col = n_warp + nt * 8 + tig * 2;
                uint32_t* o = g_qk2 + ((size_t)b * 2 * C_ + gr0) * (N_ / 2)
                              + bn * 64 + (col >> 1);
                o[0] = packh2(acc[mt][nt][0] + bi0, acc[mt][nt][1] + bi0);
                o[8 * (N_ / 2)] = packh2(acc[mt][nt][2] + bi1, acc[mt][nt][3] + bi1);
            }
        }
    } else {
        #pragma unroll
        for (int mt = 0; mt < 4; mt++) {
            int r0 = m_warp + mt * 16 + gid;
            int o_glob = bm * 128 + r0;
            float bi0 = bias[o_glob], bi1 = bias[o_glob + 8];
            int ch = (bm - 8) * 128 + m_warp + mt * 16 + gid;
            #pragma unroll
            for (int nt = 0; nt < 4; nt++) {
                int col = n_warp + nt * 8 + tig * 2;
                float v00 = acc[mt][nt][0] + bi0;
                float v01 = acc[mt][nt][1] + bi0;
                float v10 = acc[mt][nt][2] + bi1;
                float v11 = acc[mt][nt][3] + bi1;
                float n00 = __shfl_down_sync(0xFFFFFFFF, v00, 4);
                float n01 = __shfl_down_sync(0xFFFFFFFF, v01, 4);
                float n10 = __shfl_down_sync(0xFFFFFFFF, v10, 4);
                float n11 = __shfl_down_sync(0xFFFFFFFF, v11, 4);
                if (!(gid & 1)) {
                    uint32_t* o0 = g_v2 + ((size_t)b * 256 + (ch >> 1)) * N_
                                   + bn * 128 + col;
                    *(uint2*)o0 = make_uint2(packh2(v00, n00), packh2(v01, n01));
                    uint32_t* o1 = g_v2 + ((size_t)b * 256 + ((ch + 8) >> 1)) * N_
                                   + bn * 128 + col;
                    *(uint2*)o1 = make_uint2(packh2(v10, n10), packh2(v11, n11));
                }
            }
        }
    }
}

// ---------------- fp16 GEMM (out proj): 128x128, BK=32, 3-stage, 2 CTA/SM ----------------
__global__ __launch_bounds__(256, 2) void gemm_out(
    const float* __restrict__ bias, const float* __restrict__ resid,
    float* __restrict__ Out)
{
    extern __shared__ __align__(16) uint32_t smo[];
    uint32_t* As2 = smo;
    uint32_t* Bs2 = smo + 3 * 2048;

    int b = blockIdx.z, bm = blockIdx.y, bn = blockIdx.x;
    int tid = threadIdx.x, lane = tid & 31, wid = tid >> 5;
    int gid = lane >> 2, tig = lane & 3;
    int m_warp = (wid >> 2) * 64, n_warp = (wid & 3) * 32;
    int mt_base = (wid >> 2) * 4;

    uint32_t As_base = (uint32_t)__cvta_generic_to_shared(As2);
    uint32_t Bs_base = (uint32_t)__cvta_generic_to_shared(Bs2);

    float acc[4][4][4];
    #pragma unroll
    for (int mt = 0; mt < 4; mt++)
        #pragma unroll
        for (int nt = 0; nt < 4; nt++)
            #pragma unroll
            for (int r = 0; r < 4; r++) acc[mt][nt][r] = 0.f;

    auto issue = [&](int kt, int s) {
        #pragma unroll
        for (int l = 0; l < 2; l++) {
            int c = tid + l * 256;
            int mt = c >> 6, w4 = c & 63;
            cp16(As_base + ((s * 2048) + mt * 256 + w4 * 4) * 4,
                 g_wo2 + ((size_t)(bm * 8 + mt) * 32 + kt * 2) * 128 + w4 * 4);
        }
        #pragma unroll
        for (int l = 0; l < 2; l++) {
            int c = tid + l * 256;
            int r = c >> 5, n4 = c & 31;
            cp16(Bs_base + ((s * 16 + r) * BS_S + n4 * 4) * 4,
                 g_hv2 + ((size_t)b * 256 + kt * 16 + r) * N_ + bn * 128 + n4 * 4);
        }
        cp_commit();
    };

    issue(0, 0);
    issue(1, 1);
    for (int kt = 0; kt < NTK_; kt++) {
        if (kt == NTK_ - 1) cp_wait0(); else cp_wait1();
        __syncthreads();
        if (kt + 2 < NTK_) issue(kt + 2, (kt + 2) % 3);
        int buf = kt % 3;

        #pragma unroll
        for (int ks = 0; ks < 2; ks++) {
            int kb2 = ks * 8;
            uint4 af[4];
            uint32_t bf[4][2];
            #pragma unroll
            for (int mt = 0; mt < 4; mt++)
                af[mt] = *(const uint4*)(As2 + buf * 2048 +
                                         (mt_base + mt) * 256 + ks * 128 + lane * 4);
            #pragma unroll
            for (int nt = 0; nt < 4; nt++) {
                int n0 = n_warp + nt * 8 + gid;
                bf[nt][0] = Bs2[(buf * 16 + kb2 + tig) * BS_S + n0];
                bf[nt][1] = Bs2[(buf * 16 + kb2 + tig + 4) * BS_S + n0];
            }
            #pragma unroll
            for (int mt = 0; mt < 4; mt++)
                #pragma unroll
                for (int nt = 0; nt < 4; nt++)
                    mma16h(acc[mt][nt], af[mt].x, af[mt].y, af[mt].z, af[mt].w,
                           bf[nt][0], bf[nt][1]);
        }
    }

    #pragma unroll
    for (int mt = 0; mt < 4; mt++) {
        int r0 = m_warp + mt * 16 + gid;
        int gr0 = bm * 128 + r0;
        float bi0 = bias[gr0], bi1 = bias[gr0 + 8];
        #pragma unroll
        for (int nt = 0; nt < 4; nt++) {
            int col = n_warp + nt * 8 + tig * 2;
            size_t base = ((size_t)b * C_ + gr0) * N_ + bn * 128 + col;
            float2 x0 = *(const float2*)(resid + base);
            float2 x1 = *(const float2*)(resid + base + 8 * N_);
            *(float2*)(Out + base) =
                make_float2(acc[mt][nt][0] + bi0 + x0.x, acc[mt][nt][1] + bi0 + x0.y);
            *(float2*)(Out + base + 8 * N_) =
                make_float2(acc[mt][nt][2] + bi1 + x1.x, acc[mt][nt][3] + bi1 + x1.y);
        }
    }
}

// ---------------- attention ----------------
#define SQ_S 68
#define QK_S 36

__global__ __launch_bounds__(256) void attn_qk_kernel()
{
    __shared__ uint32_t q2s[64 * QK_S], k2s[64 * QK_S];
    int chunk = blockIdx.x, bh = blockIdx.y;
    int b = bh / NH_, h = bh % NH_;
    const uint32_t* q2 = g_qk2 + ((size_t)b * 2 * C_ + h * HD_) * (N_ / 2) + chunk * (NCW_ / 2);
    const uint32_t* k2 = g_qk2 + ((size_t)b * 2 * C_ + C_ + h * HD_) * (N_ / 2) + chunk * (NCW_ / 2);

    int tid = threadIdx.x, lane = tid & 31, wid = tid >> 5;
    int gid = lane >> 2, tig = lane & 3;
    int m_warp = (wid & 3) * 16, n_warp = (wid >> 2) * 32;

    float acc[4][4];
    #pragma unroll
    for (int nt = 0; nt < 4; nt++)
        #pragma unroll
        for (int r = 0; r < 4; r++) acc[nt][r] = 0.f;

    uint4 rq[2], rk[2];
    #pragma unroll
    for (int l = 0; l < 2; l++) {
        int idx = tid + l * 256, row = idx >> 3, w4 = idx & 7;
        rq[l] = *(const uint4*)(q2 + (size_t)row * (N_ / 2) + w4 * 4);
        rk[l] = *(const uint4*)(k2 + (size_t)row * (N_ / 2) + w4 * 4);
    }

    for (int n0w = 0; n0w < NCW_ / 2; n0w += 32) {
        #pragma unroll
        for (int l = 0; l < 2; l++) {
            int idx = tid + l * 256, row = idx >> 3, w4 = idx & 7;
            *(uint4*)(q2s + row * QK_S + w4 * 4) = rq[l];
            *(uint4*)(k2s + row * QK_S + w4 * 4) = rk[l];
        }
        __syncthreads();
        if (n0w + 32 < NCW_ / 2) {
            #pragma unroll
            for (int l = 0; l < 2; l++) {
                int idx = tid + l * 256, row = idx >> 3, w4 = idx & 7;
                rq[l] = *(const uint4*)(q2 + (size_t)row * (N_ / 2) + n0w + 32 + w4 * 4);
                rk[l] = *(const uint4*)(k2 + (size_t)row * (N_ / 2) + n0w + 32 + w4 * 4);
            }
        }
        #pragma unroll
        for (int ks = 0; ks < 4; ks++) {
            int kb = ks * 8;
            uint32_t a0 = q2s[(m_warp + gid) * QK_S + kb + tig];
            uint32_t a1 = q2s[(m_warp + gid + 8) * QK_S + kb + tig];
            uint32_t a2 = q2s[(m_warp + gid) * QK_S + kb + tig + 4];
            uint32_t a3 = q2s[(m_warp + gid + 8) * QK_S + kb + tig + 4];
            uint32_t bf[4][2];
            #pragma unroll
            for (int nt = 0; nt < 4; nt++) {
                int e0 = n_warp + nt * 8 + gid;
                bf[nt][0] = k2s[e0 * QK_S + kb + tig];
                bf[nt][1] = k2s[e0 * QK_S + kb + tig + 4];
            }
            #pragma unroll
            for (int nt = 0; nt < 4; nt++)
                mma16h(acc[nt], a0, a1, a2, a3, bf[nt][0], bf[nt][1]);
        }
        __syncthreads();
    }
    float* Sp = g_Sp + ((size_t)bh * NCH_ + chunk) * 4096;
    #pragma unroll
    for (int nt = 0; nt < 4; nt++) {
        int col = n_warp + nt * 8 + tig * 2, rA = m_warp + gid;
        *(float2*)(Sp + rA * 64 + col)       = make_float2(acc[nt][0], acc[nt][1]);
        *(float2*)(Sp + (rA + 8) * 64 + col) = make_float2(acc[nt][2], acc[nt][3]);
    }
}

__global__ __launch_bounds__(256) void attn_softmax_kernel()
{
    __shared__ float sS[64 * SQ_S];
    int bh = blockIdx.x, tid = threadIdx.x;
    const float* Sp = g_Sp + (size_t)bh * NCH_ * 4096;
    uint32_t* P2 = g_P2 + (size_t)bh * 2048;

    for (int i = tid * 4; i < 4096; i += 1024) {
        float4 s = *(const float4*)(Sp + i);
        #pragma unroll
        for (int c = 1; c < NCH_; c++) {
            float4 p = *(const float4*)(Sp + (size_t)c * 4096 + i);
            s.x += p.x; s.y += p.y; s.z += p.z; s.w += p.w;
        }
        int row = i >> 6, col = i & 63;
        s.x *= 0.125f; s.y *= 0.125f; s.z *= 0.125f; s.w *= 0.125f;
        *(float4*)(sS + row * SQ_S + col) = s;
    }
    __syncthreads();
    if (tid < 64) {
        int r = tid;
        float m = -1e30f;
        for (int c = 0; c < 64; c++) m = fmaxf(m, sS[r * SQ_S + c]);
        float s = 0.f, e[64];
        #pragma unroll 8
        for (int c = 0; c < 64; c++) { e[c] = __expf(sS[r * SQ_S + c] - m); s += e[c]; }
        float inv = 1.f / s;
        #pragma unroll 8
        for (int c2 = 0; c2 < 32; c2++)
            P2[r * 32 + c2] = packh2(e[2*c2] * inv, e[2*c2+1] * inv);
    }
}

__global__ __launch_bounds__(256) void attn_pv_kernel()
{
    __shared__ uint32_t p2s[64 * 36];
    __shared__ uint32_t v2s[32 * 72];
    __shared__ float    hs[64 * 66];

    int chunk = blockIdx.x, bh = blockIdx.y;
    int b = bh / NH_, h = bh % NH_;
    const uint32_t* v2 = g_v2 + ((size_t)b * 256 + h * 32) * N_ + chunk * NCW_;
    const uint32_t* P2 = g_P2 + (size_t)bh * 2048;
    uint32_t* hv2 = g_hv2 + ((size_t)b * 256 + h * 32) * N_ + chunk * NCW_;

    int tid = threadIdx.x, lane = tid & 31, wid = tid >> 5;
    int gid = lane >> 2, tig = lane & 3;
    int m_warp = (wid & 3) * 16, n_warp = (wid >> 2) * 32;

    for (int i = tid * 4; i < 2048; i += 1024) {
        int row = i >> 5, c2 = i & 31;
        *(uint4*)(p2s + row * 36 + c2) = *(const uint4*)(P2 + i);
    }
    uint4 rv[2];
    #pragma unroll
    for (int l = 0; l < 2; l++) {
        int idx = tid + l * 256, row = idx >> 4, w4 = idx & 15;
        rv[l] = *(const uint4*)(v2 + (size_t)row * N_ + w4 * 4);
    }
    __syncthreads();

    uint32_t pa[4][4];
    #pragma unroll
    for (int ks = 0; ks < 4; ks++) {
        int kc = ks * 8;
        pa[ks][0] = p2s[(m_warp + gid) * 36 + kc + tig];
        pa[ks][1] = p2s[(m_warp + gid + 8) * 36 + kc + tig];
        pa[ks][2] = p2s[(m_warp + gid) * 36 + kc + tig + 4];
        pa[ks][3] = p2s[(m_warp + gid + 8) * 36 + kc + tig + 4];
    }

    for (int n0 = 0; n0 < NCW_; n0 += 64) {
        #pragma unroll
        for (int l = 0; l < 2; l++) {
            int idx = tid + l * 256, row = idx >> 4, w4 = idx & 15;
            *(uint4*)(v2s + row * 72 + w4 * 4) = rv[l];
        }
        __syncthreads();
        if (n0 + 64 < NCW_) {
            #pragma unroll
            for (int l = 0; l < 2; l++) {
                int idx = tid + l * 256, row = idx >> 4, w4 = idx & 15;
                rv[l] = *(const uint4*)(v2 + (size_t)row * N_ + n0 + 64 + w4 * 4);
            }
        }
        float a2[4][4];
        #pragma unroll
        for (int nt = 0; nt < 4; nt++)
            #pragma unroll
            for (int r = 0; r < 4; r++) a2[nt][r] = 0.f;

        #pragma unroll
        for (int ks = 0; ks < 4; ks++) {
            int kc = ks * 8;
            uint32_t bf[4][2];
            #pragma unroll
            for (int nt = 0; nt < 4; nt++) {
                int nn = n_warp + nt * 8 + gid;
                bf[nt][0] = v2s[(kc + tig) * 72 + nn];
                bf[nt][1] = v2s[(kc + tig + 4) * 72 + nn];
            }
            #pragma unroll
            for (int nt = 0; nt < 4; nt++)
                mma16h(a2[nt], pa[ks][0], pa[ks][1], pa[ks][2], pa[ks][3],
                       bf[nt][0], bf[nt][1]);
        }
        #pragma unroll
        for (int nt = 0; nt < 4; nt++) {
            int col = n_warp + nt * 8 + tig * 2, rA = m_warp + gid;
            *(float2*)(hs + rA * 66 + col)       = make_float2(a2[nt][0], a2[nt][1]);
            *(float2*)(hs + (rA + 8) * 66 + col) = make_float2(a2[nt][2], a2[nt][3]);
        }
        __syncthreads();
        int n = tid & 63, c2b = tid >> 6;
        #pragma unroll
        for (int j = 0; j < 8; j++) {
            int c2 = c2b + j * 4;
            hv2[(size_t)c2 * N_ + n0 + n] =
                packh2(hs[(2*c2) * 66 + n], hs[(2*c2+1) * 66 + n]);
        }
        __syncthreads();
    }
}

// ---------------------------------------------------------------------------
extern "C" void kernel_launch(void* const* d_in, const int* in_sizes, int n_in,
                              void* d_out, int out_size)
{
    const float* x     = (const float*)d_in[0];
    const float* gamma = (const float*)d_in[1];
    const float* beta  = (const float*)d_in[2];
    const float* w_qkv = (const float*)d_in[3];
    const float* b_qkv = (const float*)d_in[4];
    const float* w_out = (const float*)d_in[5];
    const float* b_out = (const float*)d_in[6];
    float* out = (float*)d_out;

    static int configured = 0;
    if (!configured) {
        cudaFuncSetAttribute(gemm_qkv, cudaFuncAttributeMaxDynamicSharedMemorySize, GEMM_SM);
        cudaFuncSetAttribute(gemm_out, cudaFuncAttributeMaxDynamicSharedMemorySize, GEMM_SM);
        configured = 1;
    }

    wpack_all_kernel<<<((3 * C_ * C_ / 2 + C_ * C_ / 2) / 2 + 255) / 256, 256>>>(w_qkv, w_out);
    gn_stats_kernel<<<B_ * NG_, 256>>>(x, gamma, beta);
    xpack_kernel<<<(B_ * 256 * 1024) / 256, 256>>>(x);
    bias_fold_kernel<<<dim3(3 * C_ / 8, B_), 256>>>(w_qkv, b_qkv);
    gemm_qkv<<<dim3(N_ / 128, (3 * C_) / 128, B_), 256, GEMM_SM>>>();
    attn_qk_kernel<<<dim3(NCH_, B_ * NH_), 256>>>();
    attn_softmax_kernel<<<B_ * NH_, 256>>>();
    attn_pv_kernel<<<dim3(NCH_, B_ * NH_), 256>>>();
    gemm_out<<<dim3(N_ / 128, C_ / 128, B_), 256, GEMM_SM>>>(b_out, x, out);
}

// round 17
// speedup vs baseline: 1.1814x; 1.0425x over previous
#include <cuda_runtime.h>
#include <cuda_bf16.h>
#include <cuda_fp16.h>
#include <math.h>
#include <stdint.h>

#define B_   16
#define C_   512
#define N_   4096
#define NH_  8
#define HD_  64
#define NG_  8
#define CPG_ 64
#define EPS_ 1e-5f
#define NCH_ 8
#define NCW_ (N_ / NCH_)
#define NTK_ 8                                     // k-tiles of 64

#define BS_S 136                                   // Bs word stride: 8 mod 32 -> conflict-free
#define GEMM_SM ((2 * 4096 + 2 * 32 * BS_S) * 4)   // 67584 B (2-stage, BK=64)

// Scratch (allocation-free: static device globals)
__device__ uint32_t g_qk2[(size_t)B_ * 2 * C_ * (N_/2)];  // q,k fp16x2 n-pairs
__device__ uint32_t g_v2 [(size_t)B_ * (C_/2) * N_];      // v fp16x2 e-pairs
__device__ uint32_t g_hv2[(size_t)B_ * (C_/2) * N_];      // hv fp16x2 c-pairs
__device__ uint32_t g_x2 [(size_t)B_ * (C_/2) * N_];      // (sc*x) fp16x2 c-pairs
__device__ float    g_sc[B_ * C_], g_sf[B_ * C_];
__device__ uint32_t g_wqh[3 * C_ * C_ / 2];               // w_qkv fp16 frag-packed
__device__ float    g_bqb[B_ * 3 * C_];
__device__ uint32_t g_wo2[C_ * C_ / 2];                   // w_out fp16 frag-packed
__device__ float    g_Sp[(size_t)B_ * NH_ * NCH_ * 64 * 64];
__device__ uint32_t g_P2[(size_t)B_ * NH_ * 64 * 32];     // P fp16x2 e-pairs

// ---------------- helpers ----------------
__device__ __forceinline__ void mma16h(float c[4], uint32_t a0, uint32_t a1,
                                       uint32_t a2, uint32_t a3,
                                       uint32_t b0, uint32_t b1) {
    asm volatile(
        "mma.sync.aligned.m16n8k16.row.col.f32.f16.f16.f32 "
        "{%0,%1,%2,%3}, {%4,%5,%6,%7}, {%8,%9}, {%0,%1,%2,%3};\n"
        : "+f"(c[0]), "+f"(c[1]), "+f"(c[2]), "+f"(c[3])
        : "r"(a0), "r"(a1), "r"(a2), "r"(a3), "r"(b0), "r"(b1));
}
__device__ __forceinline__ void cp16(uint32_t dst, const void* src) {
    asm volatile("cp.async.cg.shared.global [%0], [%1], 16;\n" :: "r"(dst), "l"(src));
}
__device__ __forceinline__ void cp_commit() {
    asm volatile("cp.async.commit_group;\n" ::: "memory");
}
__device__ __forceinline__ void cp_wait0() {
    asm volatile("cp.async.wait_group 0;\n" ::: "memory");
}
__device__ __forceinline__ uint32_t packh2(float lo, float hi) {
    __half2 v = __floats2half2_rn(lo, hi);
    return *(uint32_t*)&v;
}

// ---------------- kernel 1: groupnorm stats -> sc/sf ----------------
__global__ __launch_bounds__(256) void gn_stats_kernel(
    const float* __restrict__ x, const float* __restrict__ gamma,
    const float* __restrict__ beta)
{
    int bg = blockIdx.x, b = bg / NG_, g = bg % NG_;
    int tid = threadIdx.x;
    const float4* xp = (const float4*)(x + ((size_t)b * C_ + (size_t)g * CPG_) * N_);
    const int total4 = CPG_ * N_ / 4;

    float s = 0.f, ss = 0.f;
    for (int i = tid; i < total4; i += 256) {
        float4 v = xp[i];
        s += v.x + v.y + v.z + v.w;
        ss += v.x*v.x + v.y*v.y + v.z*v.z + v.w*v.w;
    }
    __shared__ float sh_s[256], sh_q[256];
    sh_s[tid] = s; sh_q[tid] = ss;
    __syncthreads();
    for (int off = 128; off > 0; off >>= 1) {
        if (tid < off) { sh_s[tid] += sh_s[tid+off]; sh_q[tid] += sh_q[tid+off]; }
        __syncthreads();
    }
    float inv_n = 1.f / (float)(CPG_ * N_);
    float mean = sh_s[0] * inv_n;
    float rstd = rsqrtf(sh_q[0] * inv_n - mean * mean + EPS_);
    if (tid < CPG_) {
        int c = g * CPG_ + tid;
        float ga = gamma[c];
        g_sc[b * C_ + c] = rstd * ga;
        g_sf[b * C_ + c] = beta[c] - mean * rstd * ga;
    }
}

// ---------------- kernel 2a: pack w_qkv AND w_out -> fp16 frag layout ----------------
__device__ __forceinline__ void pack_pair(uint32_t* dst, const float* W, int w) {
    int sel = w & 3, lane_p = (w >> 2) & 31, kt_g = (w >> 7) & 31, mt_g = w >> 12;
    int gid = lane_p >> 2, tig = lane_p & 3;
    int row = mt_g * 16 + gid + ((sel & 1) << 3);
    int k = kt_g * 16 + tig * 2 + ((sel >> 1) << 3);
    dst[w] = packh2(W[(size_t)row * C_ + k], W[(size_t)row * C_ + k + 1]);
}
__global__ __launch_bounds__(256) void wpack_all_kernel(
    const float* __restrict__ Wq, const float* __restrict__ Wo)
{
    const int NQ = 3 * C_ * C_ / 2;
    const int NO = C_ * C_ / 2;
    int t = blockIdx.x * 256 + threadIdx.x;
    int w0 = t * 2;
    if (w0 + 1 < NQ) {
        pack_pair(g_wqh, Wq, w0);
        pack_pair(g_wqh, Wq, w0 + 1);
    } else if (w0 >= NQ && w0 - NQ + 1 < NO) {
        pack_pair(g_wo2, Wo, w0 - NQ);
        pack_pair(g_wo2, Wo, w0 - NQ + 1);
    }
}

// ---------------- kernel 2b: bias fold  b' = bq + W @ sf ----------------
__global__ __launch_bounds__(256) void bias_fold_kernel(
    const float* __restrict__ W, const float* __restrict__ bq)
{
    int b = blockIdx.y;
    int wid = threadIdx.x >> 5, lane = threadIdx.x & 31;
    int o = blockIdx.x * 8 + wid;
    const float* sfl = g_sf + b * C_;
    float acc = 0.f;
    for (int j = 0; j < 16; j++) {
        int c = j * 32 + lane;
        acc += W[(size_t)o * C_ + c] * sfl[c];
    }
    #pragma unroll
    for (int off = 16; off > 0; off >>= 1)
        acc += __shfl_xor_sync(0xFFFFFFFF, acc, off);
    if (lane == 0) g_bqb[b * 3 * C_ + o] = bq[o] + acc;
}

// ---------------- kernel 2c: x -> (sc*x) fp16x2 c-pair packed ----------------
__global__ __launch_bounds__(256) void xpack_kernel(const float* __restrict__ x)
{
    int idx = blockIdx.x * 256 + threadIdx.x;
    int b = idx >> 18;
    int rem = idx & 0x3FFFF;
    int c2 = rem >> 10, n4 = rem & 1023;
    float s0 = g_sc[b * C_ + 2 * c2], s1 = g_sc[b * C_ + 2 * c2 + 1];
    const float* r0 = x + ((size_t)b * C_ + 2 * c2) * N_ + n4 * 4;
    float4 v0 = *(const float4*)r0;
    float4 v1 = *(const float4*)(r0 + N_);
    uint4 o;
    o.x = packh2(v0.x * s0, v1.x * s1); o.y = packh2(v0.y * s0, v1.y * s1);
    o.z = packh2(v0.z * s0, v1.z * s1); o.w = packh2(v0.w * s0, v1.w * s1);
    *(uint4*)(g_x2 + ((size_t)b * 256 + c2) * N_ + n4 * 4) = o;
}

// ---------------- fp16 GEMM (qkv): 128x128, BK=64, 2-stage, 2 CTA/SM ----------------
__global__ __launch_bounds__(256, 2) void gemm_qkv(void)
{
    extern __shared__ __align__(16) uint32_t smq[];
    uint32_t* As2 = smq;                    // 2*4096 words
    uint32_t* Bs2 = smq + 2 * 4096;         // 2*32*BS_S words

    int b = blockIdx.z, bm = blockIdx.y, bn = blockIdx.x;
    const float* bias = g_bqb + b * 3 * C_;

    int tid = threadIdx.x, lane = tid & 31, wid = tid >> 5;
    int gid = lane >> 2, tig = lane & 3;
    int m_warp = (wid >> 2) * 64, n_warp = (wid & 3) * 32;
    int mt_base = (wid >> 2) * 4;

    uint32_t As_base = (uint32_t)__cvta_generic_to_shared(As2);
    uint32_t Bs_base = (uint32_t)__cvta_generic_to_shared(Bs2);

    float acc[4][4][4];
    #pragma unroll
    for (int mt = 0; mt < 4; mt++)
        #pragma unroll
        for (int nt = 0; nt < 4; nt++)
            #pragma unroll
            for (int r = 0; r < 4; r++) acc[mt][nt][r] = 0.f;

    auto issue = [&](int kt, int s) {
        #pragma unroll
        for (int l = 0; l < 4; l++) {
            int c = tid + l * 256;             // 0..1023
            int mt = c >> 7, w4 = c & 127;
            cp16(As_base + ((s * 4096) + mt * 512 + w4 * 4) * 4,
                 g_wqh + ((size_t)(bm * 8 + mt) * 32 + kt * 4) * 128 + w4 * 4);
        }
        #pragma unroll
        for (int l = 0; l < 4; l++) {
            int c = tid + l * 256;
            int r = c >> 5, n4 = c & 31;       // r 0..31 (c2 rows)
            cp16(Bs_base + ((s * 32 + r) * BS_S + n4 * 4) * 4,
                 g_x2 + ((size_t)b * 256 + kt * 32 + r) * N_ + bn * 128 + n4 * 4);
        }
        cp_commit();
    };

    issue(0, 0);
    int buf = 0;
    for (int kt = 0; kt < NTK_; kt++) {
        cp_wait0();
        __syncthreads();
        if (kt + 1 < NTK_) issue(kt + 1, buf ^ 1);

        #pragma unroll
        for (int ks = 0; ks < 4; ks++) {
            int kb2 = ks * 8;
            uint4 af[4];
            uint32_t bf[4][2];
            #pragma unroll
            for (int mt = 0; mt < 4; mt++)
                af[mt] = *(const uint4*)(As2 + buf * 4096 +
                                         (mt_base + mt) * 512 + ks * 128 + lane * 4);
            #pragma unroll
            for (int nt = 0; nt < 4; nt++) {
                int n0 = n_warp + nt * 8 + gid;
                bf[nt][0] = Bs2[(buf * 32 + kb2 + tig) * BS_S + n0];
                bf[nt][1] = Bs2[(buf * 32 + kb2 + tig + 4) * BS_S + n0];
            }
            #pragma unroll
            for (int mt = 0; mt < 4; mt++)
                #pragma unroll
                for (int nt = 0; nt < 4; nt++)
                    mma16h(acc[mt][nt], af[mt].x, af[mt].y, af[mt].z, af[mt].w,
                           bf[nt][0], bf[nt][1]);
        }
        buf ^= 1;
    }

    if (bm < 8) {
        #pragma unroll
        for (int mt = 0; mt < 4; mt++) {
            int r0 = m_warp + mt * 16 + gid;
            int gr0 = bm * 128 + r0;
            float bi0 = bias[gr0], bi1 = bias[gr0 + 8];
            #pragma unroll
            for (int nt = 0; nt < 4; nt++) {
                int col = n_warp + nt * 8 + tig * 2;
                uint32_t* o = g_qk2 + ((size_t)b * 2 * C_ + gr0) * (N_ / 2)
                              + bn * 64 + (col >> 1);
                o[0] = packh2(acc[mt][nt][0] + bi0, acc[mt][nt][1] + bi0);
                o[8 * (N_ / 2)] = packh2(acc[mt][nt][2] + bi1, acc[mt][nt][3] + bi1);
            }
        }
    } else {
        #pragma unroll
        for (int mt = 0; mt < 4; mt++) {
            int r0 = m_warp + mt * 16 + gid;
            int o_glob = bm * 128 + r0;
            float bi0 = bias[o_glob], bi1 = bias[o_glob + 8];
            int ch = (bm - 8) * 128 + m_warp + mt * 16 + gid;
            #pragma unroll
            for (int nt = 0; nt < 4; nt++) {
                int col = n_warp + nt * 8 + tig * 2;
                float v00 = acc[mt][nt][0] + bi0;
                float v01 = acc[mt][nt][1] + bi0;
                float v10 = acc[mt][nt][2] + bi1;
                float v11 = acc[mt][nt][3] + bi1;
                float n00 = __shfl_down_sync(0xFFFFFFFF, v00, 4);
                float n01 = __shfl_down_sync(0xFFFFFFFF, v01, 4);
                float n10 = __shfl_down_sync(0xFFFFFFFF, v10, 4);
                float n11 = __shfl_down_sync(0xFFFFFFFF, v11, 4);
                if (!(gid & 1)) {
                    uint32_t* o0 = g_v2 + ((size_t)b * 256 + (ch >> 1)) * N_
                                   + bn * 128 + col;
                    *(uint2*)o0 = make_uint2(packh2(v00, n00), packh2(v01, n01));
                    uint32_t* o1 = g_v2 + ((size_t)b * 256 + ((ch + 8) >> 1)) * N_
                                   + bn * 128 + col;
                    *(uint2*)o1 = make_uint2(packh2(v10, n10), packh2(v11, n11));
                }
            }
        }
    }
}

// ---------------- fp16 GEMM (out proj): 128x128, BK=64, 2-stage, 2 CTA/SM ----------------
__global__ __launch_bounds__(256, 2) void gemm_out(
    const float* __restrict__ bias, const float* __restrict__ resid,
    float* __restrict__ Out)
{
    extern __shared__ __align__(16) uint32_t smo[];
    uint32_t* As2 = smo;
    uint32_t* Bs2 = smo + 2 * 4096;

    int b = blockIdx.z, bm = blockIdx.y, bn = blockIdx.x;
    int tid = threadIdx.x, lane = tid & 31, wid = tid >> 5;
    int gid = lane >> 2, tig = lane & 3;
    int m_warp = (wid >> 2) * 64, n_warp = (wid & 3) * 32;
    int mt_base = (wid >> 2) * 4;

    uint32_t As_base = (uint32_t)__cvta_generic_to_shared(As2);
    uint32_t Bs_base = (uint32_t)__cvta_generic_to_shared(Bs2);

    float acc[4][4][4];
    #pragma unroll
    for (int mt = 0; mt < 4; mt++)
        #pragma unroll
        for (int nt = 0; nt < 4; nt++)
            #pragma unroll
            for (int r = 0; r < 4; r++) acc[mt][nt][r] = 0.f;

    auto issue = [&](int kt, int s) {
        #pragma unroll
        for (int l = 0; l < 4; l++) {
            int c = tid + l * 256;
            int mt = c >> 7, w4 = c & 127;
            cp16(As_base + ((s * 4096) + mt * 512 + w4 * 4) * 4,
                 g_wo2 + ((size_t)(bm * 8 + mt) * 32 + kt * 4) * 128 + w4 * 4);
        }
        #pragma unroll
        for (int l = 0; l < 4; l++) {
            int c = tid + l * 256;
            int r = c >> 5, n4 = c & 31;
            cp16(Bs_base + ((s * 32 + r) * BS_S + n4 * 4) * 4,
                 g_hv2 + ((size_t)b * 256 + kt * 32 + r) * N_ + bn * 128 + n4 * 4);
        }
        cp_commit();
    };

    issue(0, 0);
    int buf = 0;
    for (int kt = 0; kt < NTK_; kt++) {
        cp_wait0();
        __syncthreads();
        if (kt + 1 < NTK_) issue(kt + 1, buf ^ 1);

        #pragma unroll
        for (int ks = 0; ks < 4; ks++) {
            int kb2 = ks * 8;
            uint4 af[4];
            uint32_t bf[4][2];
            #pragma unroll
            for (int mt = 0; mt < 4; mt++)
                af[mt] = *(const uint4*)(As2 + buf * 4096 +
                                         (mt_base + mt) * 512 + ks * 128 + lane * 4);
            #pragma unroll
            for (int nt = 0; nt < 4; nt++) {
                int n0 = n_warp + nt * 8 + gid;
                bf[nt][0] = Bs2[(buf * 32 + kb2 + tig) * BS_S + n0];
                bf[nt][1] = Bs2[(buf * 32 + kb2 + tig + 4) * BS_S + n0];
            }
            #pragma unroll
            for (int mt = 0; mt < 4; mt++)
                #pragma unroll
                for (int nt = 0; nt < 4; nt++)
                    mma16h(acc[mt][nt], af[mt].x, af[mt].y, af[mt].z, af[mt].w,
                           bf[nt][0], bf[nt][1]);
        }
        buf ^= 1;
    }

    #pragma unroll
    for (int mt = 0; mt < 4; mt++) {
        int r0 = m_warp + mt * 16 + gid;
        int gr0 = bm * 128 + r0;
        float bi0 = bias[gr0], bi1 = bias[gr0 + 8];
        #pragma unroll
        for (int nt = 0; nt < 4; nt++) {
            int col = n_warp + nt * 8 + tig * 2;
            size_t base = ((size_t)b * C_ + gr0) * N_ + bn * 128 + col;
            float2 x0 = *(const float2*)(resid + base);
            float2 x1 = *(const float2*)(resid + base + 8 * N_);
            *(float2*)(Out + base) =
                make_float2(acc[mt][nt][0] + bi0 + x0.x, acc[mt][nt][1] + bi0 + x0.y);
            *(float2*)(Out + base + 8 * N_) =
                make_float2(acc[mt][nt][2] + bi1 + x1.x, acc[mt][nt][3] + bi1 + x1.y);
        }
    }
}

// ---------------- attention ----------------
#define SQ_S 68
#define QK_S 36

__global__ __launch_bounds__(256) void attn_qk_kernel()
{
    __shared__ uint32_t q2s[64 * QK_S], k2s[64 * QK_S];
    int chunk = blockIdx.x, bh = blockIdx.y;
    int b = bh / NH_, h = bh % NH_;
    const uint32_t* q2 = g_qk2 + ((size_t)b * 2 * C_ + h * HD_) * (N_ / 2) + chunk * (NCW_ / 2);
    const uint32_t* k2 = g_qk2 + ((size_t)b * 2 * C_ + C_ + h * HD_) * (N_ / 2) + chunk * (NCW_ / 2);

    int tid = threadIdx.x, lane = tid & 31, wid = tid >> 5;
    int gid = lane >> 2, tig = lane & 3;
    int m_warp = (wid & 3) * 16, n_warp = (wid >> 2) * 32;

    float acc[4][4];
    #pragma unroll
    for (int nt = 0; nt < 4; nt++)
        #pragma unroll
        for (int r = 0; r < 4; r++) acc[nt][r] = 0.f;

    uint4 rq[2], rk[2];
    #pragma unroll
    for (int l = 0; l < 2; l++) {
        int idx = tid + l * 256, row = idx >> 3, w4 = idx & 7;
        rq[l] = *(const uint4*)(q2 + (size_t)row * (N_ / 2) + w4 * 4);
        rk[l] = *(const uint4*)(k2 + (size_t)row * (N_ / 2) + w4 * 4);
    }

    for (int n0w = 0; n0w < NCW_ / 2; n0w += 32) {
        #pragma unroll
        for (int l = 0; l < 2; l++) {
            int idx = tid + l * 256, row = idx >> 3, w4 = idx & 7;
            *(uint4*)(q2s + row * QK_S + w4 * 4) = rq[l];
            *(uint4*)(k2s + row * QK_S + w4 * 4) = rk[l];
        }
        __syncthreads();
        if (n0w + 32 < NCW_ / 2) {
            #pragma unroll
            for (int l = 0; l < 2; l++) {
                int idx = tid + l * 256, row = idx >> 3, w4 = idx & 7;
                rq[l] = *(const uint4*)(q2 + (size_t)row * (N_ / 2) + n0w + 32 + w4 * 4);
                rk[l] = *(const uint4*)(k2 + (size_t)row * (N_ / 2) + n0w + 32 + w4 * 4);
            }
        }
        #pragma unroll
        for (int ks = 0; ks < 4; ks++) {
            int kb = ks * 8;
            uint32_t a0 = q2s[(m_warp + gid) * QK_S + kb + tig];
            uint32_t a1 = q2s[(m_warp + gid + 8) * QK_S + kb + tig];
            uint32_t a2 = q2s[(m_warp + gid) * QK_S + kb + tig + 4];
            uint32_t a3 = q2s[(m_warp + gid + 8) * QK_S + kb + tig + 4];
            uint32_t bf[4][2];
            #pragma unroll
            for (int nt = 0; nt < 4; nt++) {
                int e0 = n_warp + nt * 8 + gid;
                bf[nt][0] = k2s[e0 * QK_S + kb + tig];
                bf[nt][1] = k2s[e0 * QK_S + kb + tig + 4];
            }
            #pragma unroll
            for (int nt = 0; nt < 4; nt++)
                mma16h(acc[nt], a0, a1, a2, a3, bf[nt][0], bf[nt][1]);
        }
        __syncthreads();
    }
    float* Sp = g_Sp + ((size_t)bh * NCH_ + chunk) * 4096;
    #pragma unroll
    for (int nt = 0; nt < 4; nt++) {
        int col = n_warp + nt * 8 + tig * 2, rA = m_warp + gid;
        *(float2*)(Sp + rA * 64 + col)       = make_float2(acc[nt][0], acc[nt][1]);
        *(float2*)(Sp + (rA + 8) * 64 + col) = make_float2(acc[nt][2], acc[nt][3]);
    }
}

__global__ __launch_bounds__(256) void attn_softmax_kernel()
{
    __shared__ float sS[64 * SQ_S];
    int bh = blockIdx.x, tid = threadIdx.x;
    const float* Sp = g_Sp + (size_t)bh * NCH_ * 4096;
    uint32_t* P2 = g_P2 + (size_t)bh * 2048;

    for (int i = tid * 4; i < 4096; i += 1024) {
        float4 s = *(const float4*)(Sp + i);
        #pragma unroll
        for (int c = 1; c < NCH_; c++) {
            float4 p = *(const float4*)(Sp + (size_t)c * 4096 + i);
            s.x += p.x; s.y += p.y; s.z += p.z; s.w += p.w;
        }
        int row = i >> 6, col = i & 63;
        s.x *= 0.125f; s.y *= 0.125f; s.z *= 0.125f; s.w *= 0.125f;
        *(float4*)(sS + row * SQ_S + col) = s;
    }
    __syncthreads();
    if (tid < 64) {
        int r = tid;
        float m = -1e30f;
        for (int c = 0; c < 64; c++) m = fmaxf(m, sS[r * SQ_S + c]);
        float s = 0.f, e[64];
        #pragma unroll 8
        for (int c = 0; c < 64; c++) { e[c] = __expf(sS[r * SQ_S + c] - m); s += e[c]; }
        float inv = 1.f / s;
        #pragma unroll 8
        for (int c2 = 0; c2 < 32; c2++)
            P2[r * 32 + c2] = packh2(e[2*c2] * inv, e[2*c2+1] * inv);
    }
}

__global__ __launch_bounds__(256) void attn_pv_kernel()
{
    __shared__ uint32_t p2s[64 * 36];
    __shared__ uint32_t v2s[32 * 72];
    __shared__ float    hs[64 * 66];

    int chunk = blockIdx.x, bh = blockIdx.y;
    int b = bh / NH_, h = bh % NH_;
    const uint32_t* v2 = g_v2 + ((size_t)b * 256 + h * 32) * N_ + chunk * NCW_;
    const uint32_t* P2 = g_P2 + (size_t)bh * 2048;
    uint32_t* hv2 = g_hv2 + ((size_t)b * 256 + h * 32) * N_ + chunk * NCW_;

    int tid = threadIdx.x, lane = tid & 31, wid = tid >> 5;
    int gid = lane >> 2, tig = lane & 3;
    int m_warp = (wid & 3) * 16, n_warp = (wid >> 2) * 32;

    for (int i = tid * 4; i < 2048; i += 1024) {
        int row = i >> 5, c2 = i & 31;
        *(uint4*)(p2s + row * 36 + c2) = *(const uint4*)(P2 + i);
    }
    uint4 rv[2];
    #pragma unroll
    for (int l = 0; l < 2; l++) {
        int idx = tid + l * 256, row = idx >> 4, w4 = idx & 15;
        rv[l] = *(const uint4*)(v2 + (size_t)row * N_ + w4 * 4);
    }
    __syncthreads();

    uint32_t pa[4][4];
    #pragma unroll
    for (int ks = 0; ks < 4; ks++) {
        int kc = ks * 8;
        pa[ks][0] = p2s[(m_warp + gid) * 36 + kc + tig];
        pa[ks][1] = p2s[(m_warp + gid + 8) * 36 + kc + tig];
        pa[ks][2] = p2s[(m_warp + gid) * 36 + kc + tig + 4];
        pa[ks][3] = p2s[(m_warp + gid + 8) * 36 + kc + tig + 4];
    }

    for (int n0 = 0; n0 < NCW_; n0 += 64) {
        #pragma unroll
        for (int l = 0; l < 2; l++) {
            int idx = tid + l * 256, row = idx >> 4, w4 = idx & 15;
            *(uint4*)(v2s + row * 72 + w4 * 4) = rv[l];
        }
        __syncthreads();
        if (n0 + 64 < NCW_) {
            #pragma unroll
            for (int l = 0; l < 2; l++) {
                int idx = tid + l * 256, row = idx >> 4, w4 = idx & 15;
                rv[l] = *(const uint4*)(v2 + (size_t)row * N_ + n0 + 64 + w4 * 4);
            }
        }
        float a2[4][4];
        #pragma unroll
        for (int nt = 0; nt < 4; nt++)
            #pragma unroll
            for (int r = 0; r < 4; r++) a2[nt][r] = 0.f;

        #pragma unroll
        for (int ks = 0; ks < 4; ks++) {
            int kc = ks * 8;
            uint32_t bf[4][2];
            #pragma unroll
            for (int nt = 0; nt < 4; nt++) {
                int nn = n_warp + nt * 8 + gid;
                bf[nt][0] = v2s[(kc + tig) * 72 + nn];
                bf[nt][1] = v2s[(kc + tig + 4) * 72 + nn];
            }
            #pragma unroll
            for (int nt = 0; nt < 4; nt++)
                mma16h(a2[nt], pa[ks][0], pa[ks][1], pa[ks][2], pa[ks][3],
                       bf[nt][0], bf[nt][1]);
        }
        #pragma unroll
        for (int nt = 0; nt < 4; nt++) {
            int col = n_warp + nt * 8 + tig * 2, rA = m_warp + gid;
            *(float2*)(hs + rA * 66 + col)       = make_float2(a2[nt][0], a2[nt][1]);
            *(float2*)(hs + (rA + 8) * 66 + col) = make_float2(a2[nt][2], a2[nt][3]);
        }
        __syncthreads();
        int n = tid & 63, c2b = tid >> 6;
        #pragma unroll
        for (int j = 0; j < 8; j++) {
            int c2 = c2b + j * 4;
            hv2[(size_t)c2 * N_ + n0 + n] =
                packh2(hs[(2*c2) * 66 + n], hs[(2*c2+1) * 66 + n]);
        }
        __syncthreads();
    }
}

// ---------------------------------------------------------------------------
extern "C" void kernel_launch(void* const* d_in, const int* in_sizes, int n_in,
                              void* d_out, int out_size)
{
    const float* x     = (const float*)d_in[0];
    const float* gamma = (const float*)d_in[1];
    const float* beta  = (const float*)d_in[2];
    const float* w_qkv = (const float*)d_in[3];
    const float* b_qkv = (const float*)d_in[4];
    const float* w_out = (const float*)d_in[5];
    const float* b_out = (const float*)d_in[6];
    float* out = (float*)d_out;

    static int configured = 0;
    if (!configured) {
        cudaFuncSetAttribute(gemm_qkv, cudaFuncAttributeMaxDynamicSharedMemorySize, GEMM_SM);
        cudaFuncSetAttribute(gemm_out, cudaFuncAttributeMaxDynamicSharedMemorySize, GEMM_SM);
        configured = 1;
    }

    wpack_all_kernel<<<((3 * C_ * C_ / 2 + C_ * C_ / 2) / 2 + 255) / 256, 256>>>(w_qkv, w_out);
    gn_stats_kernel<<<B_ * NG_, 256>>>(x, gamma, beta);
    xpack_kernel<<<(B_ * 256 * 1024) / 256, 256>>>(x);
    bias_fold_kernel<<<dim3(3 * C_ / 8, B_), 256>>>(w_qkv, b_qkv);
    gemm_qkv<<<dim3(N_ / 128, (3 * C_) / 128, B_), 256, GEMM_SM>>>();
    attn_qk_kernel<<<dim3(NCH_, B_ * NH_), 256>>>();
    attn_softmax_kernel<<<B_ * NH_, 256>>>();
    attn_pv_kernel<<<dim3(NCH_, B_ * NH_), 256>>>();
    gemm_out<<<dim3(N_ / 128, C_ / 128, B_), 256, GEMM_SM>>>(b_out, x, out);
}